// round 15
// baseline (speedup 1.0000x reference)
#include <cuda_runtime.h>
#include <math.h>

#define NB 16
#define NP 32768
#define NG 32
#define NC 81
#define TPB 256                         // threads per main block (4 per row)
#define TILE_ROWS 64                    // rows per tile
#define TILE_FLOATS (TILE_ROWS * NC)    // 5184 floats
#define TILE_F4 (TILE_FLOATS / 4)       // 1296 float4
#define TILE_BYTES (TILE_FLOATS * 4)    // 20736 B
#define NTILES (NB * NP / TILE_ROWS)    // 8192
#define TILES_PER_IMG (NP / TILE_ROWS)  // 512
#define GRID 740                        // 5 blocks per SM on 148 SMs
#define NBINH 16384
#define BIN_BASE 0x3C000000             // float bits of 2^-7 (< 1/81)
#define BIN_SHIFT 12
#define BINS_PER_T 16                   // bins/thread in 1024-thread select

// Scratch (device globals). All accumulators/counters self-reset each run.
__device__ unsigned g_hist[NB * NBINH];   // per-image per-bin counts
__device__ float    g_lsum[NB * NBINH];   // per-image per-bin sum of log1p(v)
__device__ float    g_pm[NB];             // per-image matches_loss
__device__ float    g_pl[NB];             // per-image loc_loss
__device__ int      g_pt[NB];             // per-image total
__device__ float    g_res[NB];
__device__ float    g_tot[NB];
__device__ unsigned g_ctr = 0;

static __device__ __forceinline__ float warp_sum(float v) {
    #pragma unroll
    for (int o = 16; o; o >>= 1) v += __shfl_xor_sync(0xffffffffu, v, o);
    return v;
}
static __device__ __forceinline__ void warp_sum2(float& a, float& b) {
    #pragma unroll
    for (int o = 16; o; o >>= 1) {
        float aa = __shfl_xor_sync(0xffffffffu, a, o);
        float bb = __shfl_xor_sync(0xffffffffu, b, o);
        a += aa; b += bb;
    }
}
static __device__ __forceinline__ int val_bin(float v) {
    int bin = ((int)__float_as_uint(v) - BIN_BASE) >> BIN_SHIFT;
    return bin < 0 ? 0 : (bin > NBINH - 1 ? NBINH - 1 : bin);
}

// Streaming main kernel, FOUR THREADS PER ROW, 5 blocks/SM (10 warps/SMSP).
// 740 blocks grid-stride over 8192 tiles; cp.async double-buffer prefetch.
__global__ __launch_bounds__(TPB, 5) void main_kernel(
    const float4* __restrict__ pboxes,   // (B,P,4)
    const float*  __restrict__ conf,     // (B,P,C)
    const float4* __restrict__ gboxes,   // (B,G,4)
    const int*    __restrict__ glab)     // (B,G)
{
    extern __shared__ float s_buf[];     // 2 * TILE_FLOATS floats = 41472 B
    __shared__ float4 s_g[NG];
    __shared__ float  s_ga[NG];
    __shared__ int    s_gl[NG];
    __shared__ float  s_ra[8], s_rb[8];
    __shared__ int    s_rt[8];

    const int tid  = threadIdx.x;
    const int lane = tid & 31, warp = tid >> 5;
    const int rp   = tid >> 2;           // row within tile (0..63)
    const int q    = tid & 3;            // quarter: cols q*20..q*20+19 (+80 for q3)
    const int cbase = q * 20;

    const unsigned sb0 = (unsigned)__cvta_generic_to_shared(s_buf);
    #define CP_LOAD(t, bufi)                                                    \
        do {                                                                    \
            const char* _src = (const char*)conf + (size_t)(t) * TILE_BYTES;    \
            unsigned _dst = sb0 + (bufi) * TILE_BYTES;                          \
            for (int _i = tid; _i < TILE_F4; _i += TPB)                         \
                asm volatile("cp.async.cg.shared.global [%0], [%1], 16;"        \
                             :: "r"(_dst + _i * 16), "l"(_src + (size_t)_i * 16)); \
            asm volatile("cp.async.commit_group;");                             \
        } while (0)

    int t   = blockIdx.x;
    int cur = 0;
    CP_LOAD(t, 0);

    while (t < NTILES) {
        const int tn = t + GRID;
        if (tn < NTILES) {
            CP_LOAD(tn, cur ^ 1);
            asm volatile("cp.async.wait_group 1;" ::: "memory");
        } else {
            asm volatile("cp.async.wait_group 0;" ::: "memory");
        }

        const int b = t / TILES_PER_IMG;
        if (tid < NG) {                  // (re)load gt data for this image
            float4 g = gboxes[b * NG + tid];
            s_g[tid]  = g;
            s_ga[tid] = fmaxf(g.z - g.x, 0.f) * fmaxf(g.w - g.y, 0.f);
            s_gl[tid] = glab[b * NG + tid];
        }
        __syncthreads();

        const float* r = s_buf + cur * TILE_FLOATS + rp * NC;

        // raw-exp softmax stats over this thread's 20(+1) columns, 4-way ILP
        float s0 = 0.f, s1 = 0.f, s2 = 0.f, s3 = 0.f;
        float m0 = -1e30f, m1 = -1e30f, m2 = -1e30f, m3 = -1e30f;
        #pragma unroll
        for (int j = 0; j < 20; j += 4) {
            float x0 = r[cbase + j],     x1 = r[cbase + j + 1];
            float x2 = r[cbase + j + 2], x3 = r[cbase + j + 3];
            s0 += __expf(x0); s1 += __expf(x1); s2 += __expf(x2); s3 += __expf(x3);
            m0 = fmaxf(m0, x0); m1 = fmaxf(m1, x1);
            m2 = fmaxf(m2, x2); m3 = fmaxf(m3, x3);
        }
        if (q == 3) { float x = r[80]; s0 += __expf(x); m0 = fmaxf(m0, x); }
        float ssum = (s0 + s1) + (s2 + s3);
        float mmax = fmaxf(fmaxf(m0, m1), fmaxf(m2, m3));

        // 4-way combine within the row (partners lane^1, lane^2)
        ssum += __shfl_xor_sync(0xffffffffu, ssum, 1);
        mmax = fmaxf(mmax, __shfl_xor_sync(0xffffffffu, mmax, 1));
        ssum += __shfl_xor_sync(0xffffffffu, ssum, 2);
        mmax = fmaxf(mmax, __shfl_xor_sync(0xffffffffu, mmax, 2));
        float lse   = __logf(ssum);
        float smmax = __fdividef(__expf(mmax), ssum);

        // IoU vs this thread's 8 gt boxes
        const int row = t * TILE_ROWS + rp;
        float4 pb = pboxes[row];
        float pa = fmaxf(pb.z - pb.x, 0.f) * fmaxf(pb.w - pb.y, 0.f);
        float mc = 0.f, lc = 0.f;
        int   tc = 0, anyi = 0;
        #pragma unroll
        for (int j = 0; j < 8; ++j) {
            int g = q * 8 + j;
            float4 gb = s_g[g];
            float ltx = fmaxf(pb.x, gb.x), lty = fmaxf(pb.y, gb.y);
            float rbx = fminf(pb.z, gb.z), rby = fminf(pb.w, gb.w);
            float inter = fmaxf(rbx - ltx, 0.f) * fmaxf(rby - lty, 0.f);
            float uni = pa + s_ga[g] - inter;
            if (inter > 0.5f * fmaxf(uni, 1e-9f)) {  // iou > 0.5, division-free
                anyi = 1; ++tc;
                mc += r[s_gl[g]] - lse;              // full row visible in smem
                float sl = 0.f, d, ad;
                d = pb.x - gb.x; ad = fabsf(d); sl += (ad < 1.f) ? 0.5f * d * d : ad - 0.5f;
                d = pb.y - gb.y; ad = fabsf(d); sl += (ad < 1.f) ? 0.5f * d * d : ad - 0.5f;
                d = pb.z - gb.z; ad = fabsf(d); sl += (ad < 1.f) ? 0.5f * d * d : ad - 0.5f;
                d = pb.w - gb.w; ad = fabsf(d); sl += (ad < 1.f) ? 0.5f * d * d : ad - 0.5f;
                lc += sl * 0.25f;
            }
        }
        // 4-way combine of match results
        mc  += __shfl_xor_sync(0xffffffffu, mc, 1);
        lc  += __shfl_xor_sync(0xffffffffu, lc, 1);
        tc  += __shfl_xor_sync(0xffffffffu, tc, 1);
        anyi |= __shfl_xor_sync(0xffffffffu, anyi, 1);
        mc  += __shfl_xor_sync(0xffffffffu, mc, 2);
        lc  += __shfl_xor_sync(0xffffffffu, lc, 2);
        tc  += __shfl_xor_sync(0xffffffffu, tc, 2);
        anyi |= __shfl_xor_sync(0xffffffffu, anyi, 2);

        if (q == 0) {
            float myneg = anyi ? 0.f : smmax;
            int bin = val_bin(myneg);
            atomicAdd(&g_hist[b * NBINH + bin], 1u);
            atomicAdd(&g_lsum[b * NBINH + bin], __logf(1.f + myneg));
        } else {
            mc = 0.f; lc = 0.f; tc = 0;       // count pair totals once
        }

        warp_sum2(mc, lc);
        unsigned tcu = __reduce_add_sync(0xffffffffu, (unsigned)tc);
        if (lane == 0) { s_ra[warp] = mc; s_rb[warp] = lc; s_rt[warp] = (int)tcu; }
        __syncthreads();                      // also frees buffer `cur`
        if (tid == 0) {
            float M = 0.f, L = 0.f; int T = 0;
            #pragma unroll
            for (int w = 0; w < 8; ++w) { M += s_ra[w]; L += s_rb[w]; T += s_rt[w]; }
            if (T) {
                atomicAdd(&g_pm[b], M);
                atomicAdd(&g_pl[b], L);
                atomicAdd(&g_pt[b], T);
            }
        }
        cur ^= 1;
        t = tn;
    }
    #undef CP_LOAD
}

// One 1024-thread block per image: suffix-scan of counts -> exact boundary bin
// D + krem; nomatch = sum of per-bin log1p-sums for bins > D plus
// krem * (lsum[D] / hist[D]) for the boundary bin. No element sweep at all.
__global__ __launch_bounds__(1024) void select_kernel(float* __restrict__ out)
{
    __shared__ unsigned s_wsum[32], s_wabove[32];
    __shared__ float    s_red[32];
    __shared__ float    s_M, s_L;
    __shared__ int      s_k, s_D;
    __shared__ unsigned s_krem;
    __shared__ int      s_done;

    const int b = blockIdx.x, tid = threadIdx.x;
    const int lane = tid & 31, warp = tid >> 5;

    if (tid == 0) {
        float M = g_pm[b], L = g_pl[b];
        int   T = g_pt[b];
        s_M = M; s_L = L;
        int k = 3 * T;
        if (k > NP) k = NP;
        s_k = k;
        g_tot[b] = (float)T;
        g_pm[b] = 0.f; g_pl[b] = 0.f; g_pt[b] = 0;      // reset for next replay
        s_D = -1; s_krem = 0u;
    }
    __syncthreads();

    const unsigned k = (unsigned)s_k;
    unsigned* hist = g_hist + (size_t)b * NBINH;
    float*    lsum = g_lsum + (size_t)b * NBINH;

    // load own 16 counts, chunk sum, block suffix-scan from the top
    unsigned cnt[BINS_PER_T];
    unsigned part = 0u;
    {
        const uint4* hb = (const uint4*)hist;
        #pragma unroll
        for (int j = 0; j < BINS_PER_T / 4; ++j) {
            uint4 v = hb[tid * (BINS_PER_T / 4) + j];
            cnt[j * 4 + 0] = v.x; cnt[j * 4 + 1] = v.y;
            cnt[j * 4 + 2] = v.z; cnt[j * 4 + 3] = v.w;
            part += v.x + v.y + v.z + v.w;
        }
    }
    unsigned incl = part;                                // warp suffix-incl
    #pragma unroll
    for (int o = 1; o < 32; o <<= 1) {
        unsigned n = __shfl_down_sync(0xffffffffu, incl, o);
        if (lane + o < 32) incl += n;
    }
    if (lane == 0) s_wsum[warp] = incl;
    __syncthreads();
    if (warp == 0) {
        unsigned wv = s_wsum[lane];
        unsigned winc = wv;
        #pragma unroll
        for (int o = 1; o < 32; o <<= 1) {
            unsigned n = __shfl_down_sync(0xffffffffu, winc, o);
            if (lane + o < 32) winc += n;
        }
        s_wabove[lane] = winc - wv;                      // warps strictly above
    }
    __syncthreads();

    if (k > 0) {
        unsigned above = s_wabove[warp] + (incl - part);
        if (above < k && above + part >= k) {            // unique boundary chunk
            unsigned cum = above;
            for (int j = BINS_PER_T - 1; j >= 0; --j) {
                unsigned c = cnt[j];
                if (cum + c >= k) { s_D = tid * BINS_PER_T + j; s_krem = k - cum; break; }
                cum += c;
            }
        }
    }
    __syncthreads();

    const int      D    = s_D;
    const unsigned krem = s_krem;

    // per-thread: sum own log1p-sums over bins > D; boundary bin averaged
    float local = 0.f;
    if (k > 0) {
        const float4* lb = (const float4*)lsum;
        float lv[BINS_PER_T];
        #pragma unroll
        for (int j = 0; j < BINS_PER_T / 4; ++j) {
            float4 v = lb[tid * (BINS_PER_T / 4) + j];
            lv[j * 4 + 0] = v.x; lv[j * 4 + 1] = v.y;
            lv[j * 4 + 2] = v.z; lv[j * 4 + 3] = v.w;
        }
        #pragma unroll
        for (int j = 0; j < BINS_PER_T; ++j) {
            int bin = tid * BINS_PER_T + j;
            if (bin > D) local += lv[j];
            else if (bin == D)
                local += (float)krem * __fdividef(lv[j], (float)cnt[j]);
        }
    }

    // reset own hist/lsum chunks (disjoint; only this thread read them)
    {
        uint4 z = make_uint4(0u, 0u, 0u, 0u);
        uint4* hw = (uint4*)hist;
        uint4* lw = (uint4*)lsum;
        #pragma unroll
        for (int j = 0; j < BINS_PER_T / 4; ++j) {
            hw[tid * (BINS_PER_T / 4) + j] = z;
            lw[tid * (BINS_PER_T / 4) + j] = z;
        }
    }

    local = warp_sum(local);
    if (lane == 0) s_red[warp] = local;
    __syncthreads();
    if (tid == 0) {
        float nm = 0.f;
        #pragma unroll
        for (int w = 0; w < 32; ++w) nm += s_red[w];
        g_res[b] = nm - s_M + s_L;
        __threadfence();
        unsigned old = atomicAdd(&g_ctr, 1u);
        s_done = (old == NB - 1) ? 1 : 0;
        if (s_done) g_ctr = 0u;                          // reset for next replay
    }
    __syncthreads();

    if (s_done && warp == 0) {
        __threadfence();
        float v = (lane < NB) ? g_res[lane] : 0.f;
        v = warp_sum(v);
        if (lane == 0) out[0] = v / g_tot[NB - 1];
    }
}

extern "C" void kernel_launch(void* const* d_in, const int* in_sizes, int n_in,
                              void* d_out, int out_size)
{
    const float4* pboxes = (const float4*)d_in[0];
    const float*  conf   = (const float*)d_in[1];
    const float4* gboxes = (const float4*)d_in[2];
    const int*    glab   = (const int*)d_in[3];

    // Unconditional (idempotent, capture-safe): 41472 B dynamic smem
    cudaFuncSetAttribute(main_kernel,
                         cudaFuncAttributeMaxDynamicSharedMemorySize,
                         2 * TILE_BYTES);

    main_kernel<<<GRID, TPB, 2 * TILE_BYTES>>>(pboxes, conf, gboxes, glab);
    select_kernel<<<NB, 1024>>>((float*)d_out);
}

// round 16
// speedup vs baseline: 1.1658x; 1.1658x over previous
#include <cuda_runtime.h>
#include <math.h>

#define NB 16
#define NP 32768
#define NG 32
#define NC 81
#define TPB 128                         // threads per main block (2 per row)
#define TILE_ROWS 64                    // rows per tile
#define TILE_FLOATS (TILE_ROWS * NC)    // 5184 floats
#define TILE_F4 (TILE_FLOATS / 4)       // 1296 float4
#define TILE_BYTES (TILE_FLOATS * 4)    // 20736 B
#define NTILES (NB * NP / TILE_ROWS)    // 8192
#define TILES_PER_IMG (NP / TILE_ROWS)  // 512
#define GRID 592                        // 4 blocks per SM on 148 SMs
#define NBINH 16384
#define BIN_BASE 0x3C000000             // float bits of 2^-7 (< 1/81)
#define BIN_SHIFT 12
#define BINS_PER_T 16                   // bins/thread in 1024-thread select

// Scratch (device globals). All accumulators/counters self-reset each run.
__device__ unsigned g_hist[NB * NBINH];   // per-image per-bin counts
__device__ float    g_lsum[NB * NBINH];   // per-image per-bin sum of log1p(v)
__device__ float    g_pm[NB];             // per-image matches_loss
__device__ float    g_pl[NB];             // per-image loc_loss
__device__ int      g_pt[NB];             // per-image total
__device__ float    g_res[NB];
__device__ float    g_tot[NB];
__device__ unsigned g_ctr = 0;

static __device__ __forceinline__ float warp_sum(float v) {
    #pragma unroll
    for (int o = 16; o; o >>= 1) v += __shfl_xor_sync(0xffffffffu, v, o);
    return v;
}
static __device__ __forceinline__ void warp_sum2(float& a, float& b) {
    #pragma unroll
    for (int o = 16; o; o >>= 1) {
        float aa = __shfl_xor_sync(0xffffffffu, a, o);
        float bb = __shfl_xor_sync(0xffffffffu, b, o);
        a += aa; b += bb;
    }
}
static __device__ __forceinline__ int val_bin(float v) {
    int bin = ((int)__float_as_uint(v) - BIN_BASE) >> BIN_SHIFT;
    return bin < 0 ? 0 : (bin > NBINH - 1 ? NBINH - 1 : bin);
}

// Streaming main kernel: TWO THREADS PER ROW, 64-row tiles, 4 blocks/SM
// (16 warps/SM in 4 independent barrier domains). cp.async double buffer.
__global__ __launch_bounds__(TPB, 4) void main_kernel(
    const float4* __restrict__ pboxes,   // (B,P,4)
    const float*  __restrict__ conf,     // (B,P,C)
    const float4* __restrict__ gboxes,   // (B,G,4)
    const int*    __restrict__ glab)     // (B,G)
{
    extern __shared__ float s_buf[];     // 2 * TILE_FLOATS floats = 41472 B
    __shared__ float4 s_g[NG];
    __shared__ float  s_ga[NG];
    __shared__ int    s_gl[NG];
    __shared__ float  s_ra[4], s_rb[4];
    __shared__ int    s_rt[4];

    const int tid  = threadIdx.x;
    const int lane = tid & 31, warp = tid >> 5;
    const int rp   = tid >> 1;           // row within tile (0..63)
    const int half = tid & 1;            // 0: cols 0..39 + 80, gt 0..15
                                         // 1: cols 40..79,     gt 16..31
    const int cbase = half * 40;

    const unsigned sb0 = (unsigned)__cvta_generic_to_shared(s_buf);
    #define CP_LOAD(t, bufi)                                                    \
        do {                                                                    \
            const char* _src = (const char*)conf + (size_t)(t) * TILE_BYTES;    \
            unsigned _dst = sb0 + (bufi) * TILE_BYTES;                          \
            for (int _i = tid; _i < TILE_F4; _i += TPB)                         \
                asm volatile("cp.async.cg.shared.global [%0], [%1], 16;"        \
                             :: "r"(_dst + _i * 16), "l"(_src + (size_t)_i * 16)); \
            asm volatile("cp.async.commit_group;");                             \
        } while (0)

    int t   = blockIdx.x;
    int cur = 0;
    CP_LOAD(t, 0);

    while (t < NTILES) {
        const int tn = t + GRID;
        if (tn < NTILES) {
            CP_LOAD(tn, cur ^ 1);
            asm volatile("cp.async.wait_group 1;" ::: "memory");
        } else {
            asm volatile("cp.async.wait_group 0;" ::: "memory");
        }

        const int b = t / TILES_PER_IMG;
        if (tid < NG) {                  // (re)load gt data for this image
            float4 g = gboxes[b * NG + tid];
            s_g[tid]  = g;
            s_ga[tid] = fmaxf(g.z - g.x, 0.f) * fmaxf(g.w - g.y, 0.f);
            s_gl[tid] = glab[b * NG + tid];
        }
        __syncthreads();

        const float* r = s_buf + cur * TILE_FLOATS + rp * NC;

        // raw-exp softmax stats over this thread's 40(+1) columns, 4-way ILP
        float s0 = 0.f, s1 = 0.f, s2 = 0.f, s3 = 0.f;
        float m0 = -1e30f, m1 = -1e30f, m2 = -1e30f, m3 = -1e30f;
        #pragma unroll
        for (int j = 0; j < 40; j += 4) {
            float x0 = r[cbase + j],     x1 = r[cbase + j + 1];
            float x2 = r[cbase + j + 2], x3 = r[cbase + j + 3];
            s0 += __expf(x0); s1 += __expf(x1); s2 += __expf(x2); s3 += __expf(x3);
            m0 = fmaxf(m0, x0); m1 = fmaxf(m1, x1);
            m2 = fmaxf(m2, x2); m3 = fmaxf(m3, x3);
        }
        if (!half) { float x = r[80]; s0 += __expf(x); m0 = fmaxf(m0, x); }
        float ssum = (s0 + s1) + (s2 + s3);
        float mmax = fmaxf(fmaxf(m0, m1), fmaxf(m2, m3));

        // pair combine (partner = lane^1)
        ssum += __shfl_xor_sync(0xffffffffu, ssum, 1);
        mmax = fmaxf(mmax, __shfl_xor_sync(0xffffffffu, mmax, 1));
        float lse   = __logf(ssum);
        float smmax = __fdividef(__expf(mmax), ssum);

        // IoU vs this thread's 16 gt boxes
        const int row = t * TILE_ROWS + rp;
        float4 pb = pboxes[row];
        float pa = fmaxf(pb.z - pb.x, 0.f) * fmaxf(pb.w - pb.y, 0.f);
        float mc = 0.f, lc = 0.f;
        int   tc = 0, anyi = 0;
        #pragma unroll 4
        for (int j = 0; j < 16; ++j) {
            int g = half * 16 + j;
            float4 gb = s_g[g];
            float ltx = fmaxf(pb.x, gb.x), lty = fmaxf(pb.y, gb.y);
            float rbx = fminf(pb.z, gb.z), rby = fminf(pb.w, gb.w);
            float inter = fmaxf(rbx - ltx, 0.f) * fmaxf(rby - lty, 0.f);
            float uni = pa + s_ga[g] - inter;
            if (inter > 0.5f * fmaxf(uni, 1e-9f)) {  // iou > 0.5, division-free
                anyi = 1; ++tc;
                mc += r[s_gl[g]] - lse;              // full row visible in smem
                float sl = 0.f, d, ad;
                d = pb.x - gb.x; ad = fabsf(d); sl += (ad < 1.f) ? 0.5f * d * d : ad - 0.5f;
                d = pb.y - gb.y; ad = fabsf(d); sl += (ad < 1.f) ? 0.5f * d * d : ad - 0.5f;
                d = pb.z - gb.z; ad = fabsf(d); sl += (ad < 1.f) ? 0.5f * d * d : ad - 0.5f;
                d = pb.w - gb.w; ad = fabsf(d); sl += (ad < 1.f) ? 0.5f * d * d : ad - 0.5f;
                lc += sl * 0.25f;
            }
        }
        // pair combine of match results
        mc  += __shfl_xor_sync(0xffffffffu, mc, 1);
        lc  += __shfl_xor_sync(0xffffffffu, lc, 1);
        tc  += __shfl_xor_sync(0xffffffffu, tc, 1);
        anyi |= __shfl_xor_sync(0xffffffffu, anyi, 1);

        if (!half) {
            float myneg = anyi ? 0.f : smmax;
            int bin = b * NBINH + val_bin(myneg);
            atomicAdd(&g_hist[bin], 1u);
            atomicAdd(&g_lsum[bin], __logf(1.f + myneg));
        } else {
            mc = 0.f; lc = 0.f; tc = 0;       // count pair totals once
        }

        warp_sum2(mc, lc);
        unsigned tcu = __reduce_add_sync(0xffffffffu, (unsigned)tc);
        if (lane == 0) { s_ra[warp] = mc; s_rb[warp] = lc; s_rt[warp] = (int)tcu; }
        __syncthreads();                      // also frees buffer `cur`
        if (tid == 0) {
            float M = s_ra[0] + s_ra[1] + s_ra[2] + s_ra[3];
            float L = s_rb[0] + s_rb[1] + s_rb[2] + s_rb[3];
            int   T = s_rt[0] + s_rt[1] + s_rt[2] + s_rt[3];
            if (T) {
                atomicAdd(&g_pm[b], M);
                atomicAdd(&g_pl[b], L);
                atomicAdd(&g_pt[b], T);
            }
        }
        cur ^= 1;
        t = tn;
    }
    #undef CP_LOAD
}

// One 1024-thread block per image: suffix-scan of counts -> exact boundary bin
// D + krem; nomatch = sum of per-bin log1p-sums for bins > D plus
// krem * (lsum[D] / hist[D]) for the boundary bin. No element sweep at all.
__global__ __launch_bounds__(1024) void select_kernel(float* __restrict__ out)
{
    __shared__ unsigned s_wsum[32], s_wabove[32];
    __shared__ float    s_red[32];
    __shared__ float    s_M, s_L;
    __shared__ int      s_k, s_D;
    __shared__ unsigned s_krem;
    __shared__ int      s_done;

    const int b = blockIdx.x, tid = threadIdx.x;
    const int lane = tid & 31, warp = tid >> 5;

    if (tid == 0) {
        float M = g_pm[b], L = g_pl[b];
        int   T = g_pt[b];
        s_M = M; s_L = L;
        int k = 3 * T;
        if (k > NP) k = NP;
        s_k = k;
        g_tot[b] = (float)T;
        g_pm[b] = 0.f; g_pl[b] = 0.f; g_pt[b] = 0;      // reset for next replay
        s_D = -1; s_krem = 0u;
    }
    __syncthreads();

    const unsigned k = (unsigned)s_k;
    unsigned* hist = g_hist + (size_t)b * NBINH;
    float*    lsum = g_lsum + (size_t)b * NBINH;

    // load own 16 counts, chunk sum, block suffix-scan from the top
    unsigned cnt[BINS_PER_T];
    unsigned part = 0u;
    {
        const uint4* hb = (const uint4*)hist;
        #pragma unroll
        for (int j = 0; j < BINS_PER_T / 4; ++j) {
            uint4 v = hb[tid * (BINS_PER_T / 4) + j];
            cnt[j * 4 + 0] = v.x; cnt[j * 4 + 1] = v.y;
            cnt[j * 4 + 2] = v.z; cnt[j * 4 + 3] = v.w;
            part += v.x + v.y + v.z + v.w;
        }
    }
    unsigned incl = part;                                // warp suffix-incl
    #pragma unroll
    for (int o = 1; o < 32; o <<= 1) {
        unsigned n = __shfl_down_sync(0xffffffffu, incl, o);
        if (lane + o < 32) incl += n;
    }
    if (lane == 0) s_wsum[warp] = incl;
    __syncthreads();
    if (warp == 0) {
        unsigned wv = s_wsum[lane];
        unsigned winc = wv;
        #pragma unroll
        for (int o = 1; o < 32; o <<= 1) {
            unsigned n = __shfl_down_sync(0xffffffffu, winc, o);
            if (lane + o < 32) winc += n;
        }
        s_wabove[lane] = winc - wv;                      // warps strictly above
    }
    __syncthreads();

    if (k > 0) {
        unsigned above = s_wabove[warp] + (incl - part);
        if (above < k && above + part >= k) {            // unique boundary chunk
            unsigned cum = above;
            for (int j = BINS_PER_T - 1; j >= 0; --j) {
                unsigned c = cnt[j];
                if (cum + c >= k) { s_D = tid * BINS_PER_T + j; s_krem = k - cum; break; }
                cum += c;
            }
        }
    }
    __syncthreads();

    const int      D    = s_D;
    const unsigned krem = s_krem;

    // per-thread: sum own log1p-sums over bins > D; boundary bin averaged
    float local = 0.f;
    if (k > 0) {
        const float4* lb = (const float4*)lsum;
        float lv[BINS_PER_T];
        #pragma unroll
        for (int j = 0; j < BINS_PER_T / 4; ++j) {
            float4 v = lb[tid * (BINS_PER_T / 4) + j];
            lv[j * 4 + 0] = v.x; lv[j * 4 + 1] = v.y;
            lv[j * 4 + 2] = v.z; lv[j * 4 + 3] = v.w;
        }
        #pragma unroll
        for (int j = 0; j < BINS_PER_T; ++j) {
            int bin = tid * BINS_PER_T + j;
            if (bin > D) local += lv[j];
            else if (bin == D)
                local += (float)krem * __fdividef(lv[j], (float)cnt[j]);
        }
    }

    // reset own hist/lsum chunks (disjoint; only this thread read them)
    {
        uint4 z = make_uint4(0u, 0u, 0u, 0u);
        uint4* hw = (uint4*)hist;
        uint4* lw = (uint4*)lsum;
        #pragma unroll
        for (int j = 0; j < BINS_PER_T / 4; ++j) {
            hw[tid * (BINS_PER_T / 4) + j] = z;
            lw[tid * (BINS_PER_T / 4) + j] = z;
        }
    }

    local = warp_sum(local);
    if (lane == 0) s_red[warp] = local;
    __syncthreads();
    if (tid == 0) {
        float nm = 0.f;
        #pragma unroll
        for (int w = 0; w < 32; ++w) nm += s_red[w];
        g_res[b] = nm - s_M + s_L;
        __threadfence();
        unsigned old = atomicAdd(&g_ctr, 1u);
        s_done = (old == NB - 1) ? 1 : 0;
        if (s_done) g_ctr = 0u;                          // reset for next replay
    }
    __syncthreads();

    if (s_done && warp == 0) {
        __threadfence();
        float v = (lane < NB) ? g_res[lane] : 0.f;
        v = warp_sum(v);
        if (lane == 0) out[0] = v / g_tot[NB - 1];
    }
}

extern "C" void kernel_launch(void* const* d_in, const int* in_sizes, int n_in,
                              void* d_out, int out_size)
{
    const float4* pboxes = (const float4*)d_in[0];
    const float*  conf   = (const float*)d_in[1];
    const float4* gboxes = (const float4*)d_in[2];
    const int*    glab   = (const int*)d_in[3];

    // Unconditional (idempotent, capture-safe): 41472 B dynamic smem
    cudaFuncSetAttribute(main_kernel,
                         cudaFuncAttributeMaxDynamicSharedMemorySize,
                         2 * TILE_BYTES);

    main_kernel<<<GRID, TPB, 2 * TILE_BYTES>>>(pboxes, conf, gboxes, glab);
    select_kernel<<<NB, 1024>>>((float*)d_out);
}